// round 8
// baseline (speedup 1.0000x reference)
#include <cuda_runtime.h>

#define TPB     256
#define NBLOCKS 1216
#define LMIN    1024     // rows shorter than this go to the corner path

// ---------------------------------------------------------------------------
// out = sum_i x[i]*c[i] + sum_{i<j} x[i]*x[j]*c2[base(i)+(j-i-1)]
// c2 = c + n, base(i) = i*(2n-1-i)/2.
//
// Main region (rows with len >= LMIN): blocks own element-balanced contiguous
// flat ranges. Per row-slice [g, s1) the coeff stream is processed in groups
// of 4 chunks of 256 floats starting at base = g & ~31, so EVERY warp load of
// c2 is 128B-aligned (1 line, 1 wavefront). j = idx + joff; x reads are L1
// hits. Interior groups are branch-free; edge groups clamp + predicate
// (block-uniform, no divergence).
// Corner region (short rows, 1.5% of elements) is spread per-element over all
// blocks with sqrt row decode.
// ---------------------------------------------------------------------------

__global__ void zero_out_kernel(float* out) {
    if (threadIdx.x == 0 && blockIdx.x == 0) out[0] = 0.0f;
}

__device__ __forceinline__ float warp_sum(float v) {
    #pragma unroll
    for (int o = 16; o > 0; o >>= 1) v += __shfl_down_sync(0xffffffffu, v, o);
    return v;
}

__global__ __launch_bounds__(TPB)
void ham_kernel(const float* __restrict__ x,
                const float* __restrict__ c,
                float* __restrict__ out,
                int n) {
    const int t = threadIdx.x;
    const int b = blockIdx.x;
    const int G = gridDim.x;
    const float* c2 = c + n;

    const int total = (n * (n - 1)) >> 1;            // 33,550,336
    const int ilong = n - LMIN;                      // 7168
    const int gc    = (ilong * (2 * n - 1 - ilong)) >> 1;  // corner start

    float sum = 0.0f;

    // degree-1 terms, spread over all blocks
    for (int k = b * TPB + t; k < n; k += G * TPB)
        sum += __ldg(x + k) * __ldg(c + k);

    // ---- main region: element-balanced contiguous range in [0, gc) ----
    const int e0 = (int)(((long long)b       * gc) / G);
    const int e1 = (int)(((long long)(b + 1) * gc) / G);

    if (e0 < e1) {
        // decode starting row (double seed + exact fixup)
        const double nd = 2.0 * (double)n - 1.0;
        int i = (int)((nd - sqrt(nd * nd - 8.0 * (double)e0)) * 0.5);
        if (i < 0) i = 0;
        if (i > n - 2) i = n - 2;
        int rb = (i * (2 * n - 1 - i)) >> 1;
        while (rb > e0) { --i; rb -= (n - 1 - i); }
        while (e0 >= rb + (n - 1 - i)) { rb += (n - 1 - i); ++i; }
        int re = rb + (n - 1 - i);

        int g = e0;
        while (g < e1) {
            const int s1 = re < e1 ? re : e1;     // this row-slice: [g, s1)
            const float xi  = __ldg(x + i);
            const int  joff = i + 1 - rb;         // j = idx + joff
            float racc = 0.0f;

            for (int base = g & ~31; base < s1; base += 4 * TPB) {
                if (base >= g && base + 4 * TPB <= s1) {
                    // interior: branch-free, 8 aligned loads in flight
                    #pragma unroll
                    for (int k = 0; k < 4; ++k) {
                        const int idx = base + k * TPB + t;
                        racc = fmaf(__ldcs(c2 + idx),
                                    __ldg(x + idx + joff), racc);
                    }
                } else {
                    // edge group: clamp addresses, predicate contribution
                    #pragma unroll
                    for (int k = 0; k < 4; ++k) {
                        const int idx = base + k * TPB + t;
                        int ic = idx < g ? g : idx;
                        ic = ic >= s1 ? s1 - 1 : ic;
                        float cv = __ldcs(c2 + ic);
                        const float xv = __ldg(x + ic + joff);
                        cv = (idx >= g && idx < s1) ? cv : 0.0f;
                        racc = fmaf(cv, xv, racc);
                    }
                }
            }
            sum = fmaf(xi, racc, sum);

            g = s1;
            if (g == re && g < e1) { ++i; rb = re; re += (n - 1 - i); }
        }
    }

    // ---- corner region [gc, total): short rows, per-element decode ----
    const double nd = 2.0 * (double)n - 1.0;
    for (int g = gc + b * TPB + t; g < total; g += G * TPB) {
        int i = (int)((nd - sqrt(nd * nd - 8.0 * (double)g)) * 0.5);
        if (i < 0) i = 0;
        if (i > n - 2) i = n - 2;
        int rb = (i * (2 * n - 1 - i)) >> 1;
        while (rb > g) { --i; rb -= (n - 1 - i); }
        while (g >= rb + (n - 1 - i)) { rb += (n - 1 - i); ++i; }
        const int j = g - rb + i + 1;
        sum = fmaf(__ldcs(c2 + g), __ldg(x + i) * __ldg(x + j), sum);
    }

    // block reduction: warp shuffle -> smem -> warp 0 -> one atomic per block
    __shared__ float wsum[TPB / 32];
    float w = warp_sum(sum);
    if ((t & 31) == 0) wsum[t >> 5] = w;
    __syncthreads();
    if (t < 32) {
        float v = (t < TPB / 32) ? wsum[t] : 0.0f;
        v = warp_sum(v);
        if (t == 0) atomicAdd(out, v);
    }
}

extern "C" void kernel_launch(void* const* d_in, const int* in_sizes, int n_in,
                              void* d_out, int out_size) {
    const float* x = (const float*)d_in[0];
    const float* c = (const float*)d_in[1];
    float* out = (float*)d_out;
    const int n = in_sizes[0];   // 8192

    zero_out_kernel<<<1, 32>>>(out);
    ham_kernel<<<NBLOCKS, TPB>>>(x, c, out, n);
}

// round 9
// speedup vs baseline: 2.1154x; 2.1154x over previous
#include <cuda_runtime.h>

#define TPB     256
#define NBLOCKS 760      // 152 SMs * 5 resident blocks (regs ~48)
#define W       512      // column-strip width (= 2 * TPB)

// ---------------------------------------------------------------------------
// out = sum_j x[j] * ( c1[j] + sum_{i<j} x[i] * c2[base(i) + (j-i-1)] )
// c2 = c + n, base(i) = i*(2n-1-i)/2  (row-major packed upper triangle).
//
// Identical structure to the R6 champion (element-balanced row-segments,
// per-thread column accumulators), with ONE change: the clean-row body is
// unrolled 8x -> 16 independent coeff loads issued per warp-stall cycle
// (tests the per-drain-batch MLP model).
// ---------------------------------------------------------------------------

__global__ void zero_out_kernel(float* out) {
    if (threadIdx.x == 0 && blockIdx.x == 0) out[0] = 0.0f;
}

__device__ __forceinline__ float warp_sum(float v) {
    #pragma unroll
    for (int o = 16; o > 0; o >>= 1) v += __shfl_down_sync(0xffffffffu, v, o);
    return v;
}

__global__ __launch_bounds__(TPB, 5)
void ham_kernel(const float* __restrict__ x,
                const float* __restrict__ c,
                float* __restrict__ out,
                int n) {
    const int t   = threadIdx.x;
    const int b   = blockIdx.x;
    const int G   = gridDim.x;
    const float* c2 = c + n;

    const int ns = n / W;                        // 16 strips
    const int U  = W * (ns * (ns + 1) / 2) - ns; // 69616 row-segments

    const int u0 = (int)(((long long)b       * U) / G);
    const int u1 = (int)(((long long)(b + 1) * U) / G);

    float sum = 0.0f;

    // degree-1 terms, spread over all blocks
    for (int k = b * TPB + t; k < n; k += G * TPB)
        sum += __ldg(x + k) * __ldg(c + k);

    // locate starting strip for unit u0
    int js = 0, Pjs = 0;
    while (Pjs + ((js + 1) * W - 1) <= u0) { Pjs += (js + 1) * W - 1; ++js; }
    int i = u0 - Pjs;
    int u = u0;

    while (u < u1) {
        const int K   = (js + 1) * W - 1;        // rows in this strip
        const int j0  = js * W;
        const int j_a = j0 + t;
        const int j_b = j_a + TPB;

        int iend = i + (u1 - u);
        if (iend > K) iend = K;
        const int iclean = (iend < j0) ? iend : j0;

        float acc0 = 0.0f, acc1 = 0.0f;
        const float* p = c2 + ((i * (2 * n - 1 - i)) >> 1) + (j_a - i - 1);

        // ---- clean rows, unroll 8: 16 independent coeff loads per drain ----
        for (; i + 8 <= iclean; ) {
            const int d  = n - 2 - i;            // row-length recurrence
            const int o1 = d;
            const int o2 = 2 * d - 1;
            const int o3 = 3 * d - 3;
            const int o4 = 4 * d - 6;
            const int o5 = 5 * d - 10;
            const int o6 = 6 * d - 15;
            const int o7 = 7 * d - 21;
            const float xi0 = __ldg(x + i);
            const float xi1 = __ldg(x + i + 1);
            const float xi2 = __ldg(x + i + 2);
            const float xi3 = __ldg(x + i + 3);
            const float xi4 = __ldg(x + i + 4);
            const float xi5 = __ldg(x + i + 5);
            const float xi6 = __ldg(x + i + 6);
            const float xi7 = __ldg(x + i + 7);
            const float a0 = __ldcs(p);           const float b0 = __ldcs(p + TPB);
            const float a1 = __ldcs(p + o1);      const float b1 = __ldcs(p + o1 + TPB);
            const float a2 = __ldcs(p + o2);      const float b2 = __ldcs(p + o2 + TPB);
            const float a3 = __ldcs(p + o3);      const float b3 = __ldcs(p + o3 + TPB);
            const float a4 = __ldcs(p + o4);      const float b4 = __ldcs(p + o4 + TPB);
            const float a5 = __ldcs(p + o5);      const float b5 = __ldcs(p + o5 + TPB);
            const float a6 = __ldcs(p + o6);      const float b6 = __ldcs(p + o6 + TPB);
            const float a7 = __ldcs(p + o7);      const float b7 = __ldcs(p + o7 + TPB);
            acc0 = fmaf(xi0, a0, acc0);  acc1 = fmaf(xi0, b0, acc1);
            acc0 = fmaf(xi1, a1, acc0);  acc1 = fmaf(xi1, b1, acc1);
            acc0 = fmaf(xi2, a2, acc0);  acc1 = fmaf(xi2, b2, acc1);
            acc0 = fmaf(xi3, a3, acc0);  acc1 = fmaf(xi3, b3, acc1);
            acc0 = fmaf(xi4, a4, acc0);  acc1 = fmaf(xi4, b4, acc1);
            acc0 = fmaf(xi5, a5, acc0);  acc1 = fmaf(xi5, b5, acc1);
            acc0 = fmaf(xi6, a6, acc0);  acc1 = fmaf(xi6, b6, acc1);
            acc0 = fmaf(xi7, a7, acc0);  acc1 = fmaf(xi7, b7, acc1);
            p += 8 * d - 28;
            i += 8;
        }
        // remainder clean rows (< 8)
        for (; i < iclean; ++i) {
            const float xi = __ldg(x + i);
            acc0 = fmaf(xi, __ldcs(p), acc0);
            acc1 = fmaf(xi, __ldcs(p + TPB), acc1);
            p += n - 2 - i;
        }
        // ---- partial rows (row crosses the diagonal inside this strip) ----
        for (; i < iend; ++i) {
            const float xi = __ldg(x + i);
            float ca = 0.0f, cb = 0.0f;
            if (j_a > i) ca = __ldcs(p);
            if (j_b > i) cb = __ldcs(p + TPB);
            acc0 = fmaf(xi, ca, acc0);
            acc1 = fmaf(xi, cb, acc1);
            p += n - 2 - i;
        }

        sum += acc0 * __ldg(x + j_a) + acc1 * __ldg(x + j_b);

        u = Pjs + i;
        if (i == K) { Pjs += K; ++js; i = 0; }
    }

    // block reduction: warp shuffle -> smem -> warp 0 -> one atomic per block
    __shared__ float wsum[TPB / 32];
    float w = warp_sum(sum);
    if ((t & 31) == 0) wsum[t >> 5] = w;
    __syncthreads();
    if (t < 32) {
        float v = (t < TPB / 32) ? wsum[t] : 0.0f;
        v = warp_sum(v);
        if (t == 0) atomicAdd(out, v);
    }
}

extern "C" void kernel_launch(void* const* d_in, const int* in_sizes, int n_in,
                              void* d_out, int out_size) {
    const float* x = (const float*)d_in[0];
    const float* c = (const float*)d_in[1];
    float* out = (float*)d_out;
    const int n = in_sizes[0];   // 8192

    zero_out_kernel<<<1, 32>>>(out);
    ham_kernel<<<NBLOCKS, TPB>>>(x, c, out, n);
}